// round 13
// baseline (speedup 1.0000x reference)
#include <cuda_runtime.h>
#include <cuda_fp16.h>

// Problem constants
#define NB   2
#define LL   2048
#define DD   1024
#define DH   64
#define NHTOT 32            // NB*HH
#define NROW 65536          // NHTOT*LL
#define QTILES 16           // LL/128

// (1/sqrt(D)) * log2(e): energies pre-scaled into base-2 domain
#define CSCALE 0.04508422002778f

// ---------------- scratch (static device allocations; no cudaMalloc) -------
static __device__ float  g_q [NROW*DH];     // tf32-rounded, pre-scaled by CSCALE
static __device__ float  g_k [NROW*DH];     // tf32-rounded
static __device__ float  g_v [NROW*DH];     // fp32 accurate
static __device__ float  g_ok[NROW*DH];     // tf32-rounded
static __device__ float  g_ov[NROW*DH];     // fp32 accurate
static __device__ float  g_de[NROW];        // diag energies (base-2 domain)
static __device__ float  g_rs[NROW];        // 1 / row softmax denom
static __device__ float  g_dp[NROW];        // diag probability
static __device__ float  g_cs[NROW];        // column sums of off-diag probs
static __device__ float  g_part[QTILES*NROW]; // per-qtile column partials
static __device__ float  g_pre[NB*LL*DD];   // pre-fc activations (tf32-rounded)
static __device__ float  g_fcwt[DD*DD];     // fc weights (tf32-rounded)

// MUFU.EX2 (fast exp2 on the MUFU pipe)
__device__ __forceinline__ float ex2(float x) {
    float r;
    asm("ex2.approx.ftz.f32 %0, %1;" : "=f"(r) : "f"(x));
    return r;
}

__device__ __forceinline__ unsigned f2tf(float x) {
    unsigned r;
    asm("cvt.rna.tf32.f32 %0, %1;" : "=r"(r) : "f"(x));
    return r;
}

__device__ __forceinline__ void mma8(float c[4], const unsigned a[4],
                                     const unsigned b[2]) {
    asm volatile(
        "mma.sync.aligned.m16n8k8.row.col.f32.tf32.tf32.f32 "
        "{%0,%1,%2,%3}, {%4,%5,%6,%7}, {%8,%9}, {%0,%1,%2,%3};\n"
        : "+f"(c[0]), "+f"(c[1]), "+f"(c[2]), "+f"(c[3])
        : "r"(a[0]), "r"(a[1]), "r"(a[2]), "r"(a[3]), "r"(b[0]), "r"(b[1]));
}

__device__ __forceinline__ void cpa16(unsigned* dst, const unsigned* src) {
    unsigned d = (unsigned)__cvta_generic_to_shared(dst);
    asm volatile("cp.async.ca.shared.global [%0], [%1], 16;" :: "r"(d), "l"(src));
}
#define CPA_COMMIT() asm volatile("cp.async.commit_group;")
#define CPA_WAIT1()  asm volatile("cp.async.wait_group 1;")
#define CPA_WAIT0()  asm volatile("cp.async.wait_group 0;")

// ---------------- K1: fused tensor-core projections ------------------------
__global__ __launch_bounds__(256) void proj_tc_kernel(
        const float* __restrict__ xq, const float* __restrict__ xk,
        const float* __restrict__ xv, const float* __restrict__ xok,
        const float* __restrict__ xov,
        const float* __restrict__ Wq, const float* __restrict__ Wk,
        const float* __restrict__ Wv) {
    extern __shared__ __align__(16) unsigned shm[];
    unsigned* xh = shm;                 // [128][68]
    unsigned* xl = shm + 128 * 68;      // [128][68] (split only)
    unsigned* Wh = xl + 128 * 68;       // [64][68]
    unsigned* Wl = Wh + 64 * 68;        // [64][68]
    int sel = blockIdx.y;
    const float* x; const float* W; float* out;
    bool split = (sel >= 3);
    switch (sel) {
        case 0: x = xq;  W = Wq; out = g_q;  break;
        case 1: x = xk;  W = Wk; out = g_k;  break;
        case 2: x = xok; W = Wk; out = g_ok; break;
        case 3: x = xv;  W = Wv; out = g_v;  break;
        default: x = xov; W = Wv; out = g_ov; break;
    }
    int tid = threadIdx.x;
    int r0 = blockIdx.x << 7;
    for (int i = tid; i < 4096; i += 256) {
        int n = i >> 6, k = i & 63;
        float w = W[i];
        unsigned hi = f2tf(w);
        Wh[n * 68 + k] = hi;
        if (split) Wl[n * 68 + k] = f2tf(w - __uint_as_float(hi));
    }
    for (int i = tid; i < 2048; i += 256) {
        int row = i >> 4, c4 = (i & 15) << 2;
        float4 v = *(const float4*)(x + (size_t)(r0 + row) * DH + c4);
        unsigned* d = xh + row * 68 + c4;
        unsigned h0 = f2tf(v.x), h1 = f2tf(v.y), h2 = f2tf(v.z), h3 = f2tf(v.w);
        d[0] = h0; d[1] = h1; d[2] = h2; d[3] = h3;
        if (split) {
            unsigned* dl = xl + row * 68 + c4;
            dl[0] = f2tf(v.x - __uint_as_float(h0));
            dl[1] = f2tf(v.y - __uint_as_float(h1));
            dl[2] = f2tf(v.z - __uint_as_float(h2));
            dl[3] = f2tf(v.w - __uint_as_float(h3));
        }
    }
    __syncthreads();
    int lane = tid & 31, wid = tid >> 5;
    int wm = wid >> 1, wn = wid & 1;
    int gi = lane >> 2, qi = lane & 3;
    float acc[2][4][4];
#pragma unroll
    for (int mt = 0; mt < 2; mt++)
#pragma unroll
        for (int nt = 0; nt < 4; nt++)
#pragma unroll
            for (int e = 0; e < 4; e++) acc[mt][nt][e] = 0.0f;
#pragma unroll
    for (int k0 = 0; k0 < DH; k0 += 8) {
        unsigned a[2][4], b[4][2];
#pragma unroll
        for (int mt = 0; mt < 2; mt++) {
            int rb = wm * 32 + mt * 16 + gi;
            a[mt][0] = xh[rb * 68 + k0 + qi];
            a[mt][1] = xh[(rb + 8) * 68 + k0 + qi];
            a[mt][2] = xh[rb * 68 + k0 + 4 + qi];
            a[mt][3] = xh[(rb + 8) * 68 + k0 + 4 + qi];
        }
#pragma unroll
        for (int nt = 0; nt < 4; nt++) {
            int nb = wn * 32 + nt * 8 + gi;
            b[nt][0] = Wh[nb * 68 + k0 + qi];
            b[nt][1] = Wh[nb * 68 + k0 + 4 + qi];
        }
#pragma unroll
        for (int mt = 0; mt < 2; mt++)
#pragma unroll
            for (int nt = 0; nt < 4; nt++)
                mma8(acc[mt][nt], a[mt], b[nt]);
        if (split) {
            unsigned al[2][4], bl[4][2];
#pragma unroll
            for (int mt = 0; mt < 2; mt++) {
                int rb = wm * 32 + mt * 16 + gi;
                al[mt][0] = xl[rb * 68 + k0 + qi];
                al[mt][1] = xl[(rb + 8) * 68 + k0 + qi];
                al[mt][2] = xl[rb * 68 + k0 + 4 + qi];
                al[mt][3] = xl[(rb + 8) * 68 + k0 + 4 + qi];
            }
#pragma unroll
            for (int nt = 0; nt < 4; nt++) {
                int nb = wn * 32 + nt * 8 + gi;
                bl[nt][0] = Wl[nb * 68 + k0 + qi];
                bl[nt][1] = Wl[nb * 68 + k0 + 4 + qi];
            }
#pragma unroll
            for (int mt = 0; mt < 2; mt++)
#pragma unroll
                for (int nt = 0; nt < 4; nt++) {
                    mma8(acc[mt][nt], a[mt], bl[nt]);
                    mma8(acc[mt][nt], al[mt], b[nt]);
                }
        }
    }
    float oscale = (sel == 0) ? CSCALE : 1.0f;
    bool rnd = (sel < 3);
#pragma unroll
    for (int mt = 0; mt < 2; mt++) {
#pragma unroll
        for (int half = 0; half < 2; half++) {
            int row = r0 + wm * 32 + mt * 16 + gi + half * 8;
            int n = row >> 15;
            int l = (row >> 4) & (LL - 1);
            int h = row & 15;
            size_t obase = ((size_t)((n << 4) + h) * LL + l) * DH;
#pragma unroll
            for (int nt = 0; nt < 4; nt++) {
                int c = wn * 32 + nt * 8 + 2 * qi;
                float v0 = acc[mt][nt][half * 2 + 0] * oscale;
                float v1 = acc[mt][nt][half * 2 + 1] * oscale;
                if (rnd) {
                    v0 = __uint_as_float(f2tf(v0));
                    v1 = __uint_as_float(f2tf(v1));
                }
                out[obase + c] = v0;
                out[obase + c + 1] = v1;
            }
        }
    }
}

// ---------------- K2a: diagonal energies q.k (one warp per row) ------------
__global__ void diag_kernel() {
    int g = blockIdx.x * 256 + threadIdx.x;
    int w = g >> 5, lane = g & 31;
    const float* qp = g_q + (size_t)w * DH;
    const float* kp = g_k + (size_t)w * DH;
    float a = qp[lane] * kp[lane] + qp[lane + 32] * kp[lane + 32];
#pragma unroll
    for (int o = 16; o; o >>= 1) a += __shfl_xor_sync(0xffffffffu, a, o);
    if (lane == 0) g_de[w] = a;
}

// ------ shared tile-MMA body for qk passes (reads qs, cur into acc) --------
#define QK_MMA(qs, cur, acc)                                                  \
    _Pragma("unroll")                                                         \
    for (int k0 = 0; k0 < DH; k0 += 8) {                                      \
        unsigned a[4][4], b[4][2];                                            \
        _Pragma("unroll")                                                     \
        for (int mt = 0; mt < 4; mt++) {                                      \
            int rb = wm * 64 + mt * 16 + gi;                                  \
            a[mt][0] = qs[rb * 68 + k0 + qi];                                 \
            a[mt][1] = qs[(rb + 8) * 68 + k0 + qi];                           \
            a[mt][2] = qs[rb * 68 + k0 + 4 + qi];                             \
            a[mt][3] = qs[(rb + 8) * 68 + k0 + 4 + qi];                       \
        }                                                                     \
        _Pragma("unroll")                                                     \
        for (int nt = 0; nt < 4; nt++) {                                      \
            int nb = wn * 32 + nt * 8 + gi;                                   \
            b[nt][0] = cur[nb * 68 + k0 + qi];                                \
            b[nt][1] = cur[nb * 68 + k0 + 4 + qi];                            \
        }                                                                     \
        _Pragma("unroll")                                                     \
        for (int mt = 0; mt < 4; mt++)                                        \
            _Pragma("unroll")                                                 \
            for (int nt = 0; nt < 4; nt++)                                    \
                mma8(acc[mt][nt], a[mt], b[nt]);                              \
    }

// ---------------- K2: pass A — row sums (no P storage) ---------------------
__global__ __launch_bounds__(256) void qkA_kernel() {
    extern __shared__ unsigned sh[];
    unsigned* qs  = sh;                    // [128][68]
    unsigned* os0 = sh + 128 * 68;         // [128][68] double buffer
    unsigned* os1 = os0 + 128 * 68;
    float* red = (float*)(os1 + 128 * 68); // [128][4]
    int nh = blockIdx.y;
    int qt = (QTILES - 1) - blockIdx.x;    // heavy blocks first
    int q0 = qt << 7;
    const unsigned* qb = (const unsigned*)g_q + (size_t)nh * LL * DH;
    const unsigned* ob = (const unsigned*)g_ok + (size_t)nh * LL * DH;
    int tid = threadIdx.x;
    int lane = tid & 31, wid = tid >> 5;
    int wm = wid >> 2, wn = wid & 3;
    int gi = lane >> 2, qi = lane & 3;

    for (int i = tid; i < 2048; i += 256) {
        int row = i >> 4, c4 = (i & 15) << 2;
        cpa16(qs + row * 68 + c4, qb + (size_t)(q0 + row) * DH + c4);
        cpa16(os0 + row * 68 + c4, ob + (size_t)row * DH + c4);
    }
    CPA_COMMIT();
    float s[8];
#pragma unroll
    for (int i = 0; i < 8; i++) s[i] = 0.0f;
    int ntile = qt + 1;
    for (int t = 0; t < ntile; t++) {
        unsigned* cur = (t & 1) ? os1 : os0;
        unsigned* nxt = (t & 1) ? os0 : os1;
        if (t + 1 < ntile) {
            for (int i = tid; i < 2048; i += 256) {
                int row = i >> 4, c4 = (i & 15) << 2;
                cpa16(nxt + row * 68 + c4,
                      ob + (size_t)((t + 1) * 128 + row) * DH + c4);
            }
            CPA_COMMIT();
            CPA_WAIT1();
        } else {
            CPA_WAIT0();
        }
        __syncthreads();
        float acc[4][4][4];
#pragma unroll
        for (int mt = 0; mt < 4; mt++)
#pragma unroll
            for (int nt = 0; nt < 4; nt++)
#pragma unroll
                for (int e = 0; e < 4; e++) acc[mt][nt][e] = 0.0f;
        QK_MMA(qs, cur, acc)
        __syncthreads();          // all warps done with cur before overwrite
        bool dt = (t == ntile - 1);
#pragma unroll
        for (int mt = 0; mt < 4; mt++) {
            int rl = wm * 64 + mt * 16 + gi;
#pragma unroll
            for (int nt = 0; nt < 4; nt++) {
                int cl = wn * 32 + nt * 8 + 2 * qi;
                float u0 = ex2(acc[mt][nt][0]);
                float u1 = ex2(acc[mt][nt][1]);
                float u2 = ex2(acc[mt][nt][2]);
                float u3 = ex2(acc[mt][nt][3]);
                if (dt) {   // causal + diagonal excluded (local coords)
                    if (cl     >= rl)     u0 = 0.0f;
                    if (cl + 1 >= rl)     u1 = 0.0f;
                    if (cl     >= rl + 8) u2 = 0.0f;
                    if (cl + 1 >= rl + 8) u3 = 0.0f;
                }
                s[mt * 2 + 0] += u0 + u1;
                s[mt * 2 + 1] += u2 + u3;
            }
        }
    }
#pragma unroll
    for (int i = 0; i < 8; i++) {
        s[i] += __shfl_xor_sync(0xffffffffu, s[i], 1);
        s[i] += __shfl_xor_sync(0xffffffffu, s[i], 2);
    }
    __syncthreads();
    if (qi == 0) {
#pragma unroll
        for (int mt = 0; mt < 4; mt++) {
            int rl = wm * 64 + mt * 16 + gi;
            red[rl * 4 + wn] = s[mt * 2 + 0];
            red[(rl + 8) * 4 + wn] = s[mt * 2 + 1];
        }
    }
    __syncthreads();
    if (tid < 128) {
        float tot = red[tid * 4] + red[tid * 4 + 1] +
                    red[tid * 4 + 2] + red[tid * 4 + 3];
        int row = nh * LL + q0 + tid;
        float ud = ex2(g_de[row]);       // already base-2 scaled
        float rinv = 1.0f / (tot + ud);
        g_rs[row] = rinv;
        g_dp[row] = ud * rinv;
    }
}

// ---------------- K3: pass B — recompute, column partials per tile ---------
__global__ __launch_bounds__(256) void qkB_kernel() {
    extern __shared__ unsigned sh[];
    unsigned* qs  = sh;
    unsigned* os0 = sh + 128 * 68;
    unsigned* os1 = os0 + 128 * 68;
    float* redB = (float*)(os1 + 128 * 68);   // [2][128]
    int nh = blockIdx.y;
    int qt = (QTILES - 1) - blockIdx.x;
    int q0 = qt << 7;
    const unsigned* qb = (const unsigned*)g_q + (size_t)nh * LL * DH;
    const unsigned* ob = (const unsigned*)g_ok + (size_t)nh * LL * DH;
    int tid = threadIdx.x;
    int lane = tid & 31, wid = tid >> 5;
    int wm = wid >> 2, wn = wid & 3;
    int gi = lane >> 2, qi = lane & 3;

    for (int i = tid; i < 2048; i += 256) {
        int row = i >> 4, c4 = (i & 15) << 2;
        cpa16(qs + row * 68 + c4, qb + (size_t)(q0 + row) * DH + c4);
        cpa16(os0 + row * 68 + c4, ob + (size_t)row * DH + c4);
    }
    CPA_COMMIT();
    float ri[8];
#pragma unroll
    for (int mt = 0; mt < 4; mt++) {
        int row = nh * LL + q0 + wm * 64 + mt * 16 + gi;
        ri[2 * mt]     = g_rs[row];
        ri[2 * mt + 1] = g_rs[row + 8];
    }
    int ntile = qt + 1;
    for (int t = 0; t < ntile; t++) {
        unsigned* cur = (t & 1) ? os1 : os0;
        unsigned* nxt = (t & 1) ? os0 : os1;
        if (t + 1 < ntile) {
            for (int i = tid; i < 2048; i += 256) {
                int row = i >> 4, c4 = (i & 15) << 2;
                cpa16(nxt + row * 68 + c4,
                      ob + (size_t)((t + 1) * 128 + row) * DH + c4);
            }
            CPA_COMMIT();
            CPA_WAIT1();
        } else {
            CPA_WAIT0();
        }
        __syncthreads();
        float acc[4][4][4];
#pragma unroll
        for (int mt = 0; mt < 4; mt++)
#pragma unroll
            for (int nt = 0; nt < 4; nt++)
#pragma unroll
                for (int e = 0; e < 4; e++) acc[mt][nt][e] = 0.0f;
        QK_MMA(qs, cur, acc)
        __syncthreads();
        bool dt = (t == ntile - 1);
        float cp0[4], cp1[4];
#pragma unroll
        for (int nt = 0; nt < 4; nt++) { cp0[nt] = 0.0f; cp1[nt] = 0.0f; }
#pragma unroll
        for (int mt = 0; mt < 4; mt++) {
            int rl = wm * 64 + mt * 16 + gi;
#pragma unroll
            for (int nt = 0; nt < 4; nt++) {
                int cl = wn * 32 + nt * 8 + 2 * qi;
                float u0 = ex2(acc[mt][nt][0]);
                float u1 = ex2(acc[mt][nt][1]);
                float u2 = ex2(acc[mt][nt][2]);
                float u3 = ex2(acc[mt][nt][3]);
                if (dt) {
                    if (cl     >= rl)     u0 = 0.0f;
                    if (cl + 1 >= rl)     u1 = 0.0f;
                    if (cl     >= rl + 8) u2 = 0.0f;
                    if (cl + 1 >= rl + 8) u3 = 0.0f;
                }
                cp0[nt] += u0 * ri[2 * mt] + u2 * ri[2 * mt + 1];
                cp1[nt] += u1 * ri[2 * mt] + u3 * ri[2 * mt + 1];
            }
        }
        // reduce over gi (rows) within warp: lanes differ by bits 2..4
#pragma unroll
        for (int nt = 0; nt < 4; nt++) {
#pragma unroll
            for (int o = 4; o <= 16; o <<= 1) {
                cp0[nt] += __shfl_xor_sync(0xffffffffu, cp0[nt], o);
                cp1[nt] += __shfl_xor_sync(0xffffffffu, cp1[nt], o);
            }
        }
        if (gi == 0) {
#pragma unroll
            for (int nt = 0; nt < 4; nt++) {
                int cl = wn * 32 + nt * 8 + 2 * qi;
                redB[wm * 128 + cl]     = cp0[nt];
                redB[wm * 128 + cl + 1] = cp1[nt];
            }
        }
        __syncthreads();
        if (tid < 128)
            g_part[((size_t)qt * NHTOT + nh) * LL + t * 128 + tid] =
                redB[tid] + redB[128 + tid];
    }
}

// ---------------- K3b: reduce qt partials into column sums -----------------
__global__ void reduceB_kernel() {
    int idx = blockIdx.x * 256 + threadIdx.x;   // < NROW
    int nh = idx >> 11;
    int l = idx & (LL - 1);
    float sum = 0.0f;
    for (int qt = l >> 7; qt < QTILES; qt++)
        sum += g_part[((size_t)qt * NHTOT + nh) * LL + l];
    g_cs[idx] = sum;
}

// ---------------- K4a: pre = diag*v + colsum*ov (tf32-rounded) -------------
__global__ void pre_kernel() {
    int idx = blockIdx.x * 256 + threadIdx.x;   // < NB*LL*DD
    int d = idx & 63;
    int h = (idx >> 6) & 15;
    int l = (idx >> 10) & (LL - 1);
    int n = idx >> 21;
    int r = ((n << 4) + h) * LL + l;
    size_t b = (size_t)r * DH + d;
    float v = g_dp[r] * g_v[b] + g_cs[r] * g_ov[b];
    g_pre[idx] = __uint_as_float(f2tf(v));
}

// ---------------- K4a': fc weight -> tf32 bits ------------------------------
__global__ void wcvt_kernel(const float* __restrict__ w) {
    int i = blockIdx.x * 256 + threadIdx.x;
    g_fcwt[i] = __uint_as_float(f2tf(w[i]));
}

// ---------------- K4b: out = pre @ fc_w^T + fc_b (tensor core, 2-buf) ------
__global__ __launch_bounds__(256) void fc_tc_kernel(
        const float* __restrict__ bias, float* __restrict__ out) {
    extern __shared__ unsigned sh[];
    unsigned* as_[2] = { sh, sh + 128 * 68 };
    unsigned* bs_[2] = { sh + 2 * 128 * 68, sh + 3 * 128 * 68 };
    const unsigned* Ap = (const unsigned*)g_pre;
    const unsigned* Bp = (const unsigned*)g_fcwt;
    int m0 = blockIdx.y << 7, o0 = blockIdx.x << 7;
    int tid = threadIdx.x;
    int lane = tid & 31, wid = tid >> 5;
    int wm = wid >> 2, wn = wid & 3;
    int gi = lane >> 2, qi = lane & 3;
    float acc[4][4][4];
#pragma unroll
    for (int mt = 0; mt < 4; mt++)
#pragma unroll
        for (int nt = 0; nt < 4; nt++)
#pragma unroll
            for (int e = 0; e < 4; e++) acc[mt][nt][e] = 0.0f;
    for (int i = tid; i < 2048; i += 256) {
        int row = i >> 4, c4 = (i & 15) << 2;
        cpa16(as_[0] + row * 68 + c4, Ap + (size_t)(m0 + row) * DD + c4);
        cpa16(bs_[0] + row * 68 + c4, Bp + (size_t)(o0 + row) * DD + c4);
    }
    CPA_COMMIT();
    const int NT = DD / 64;
    for (int t = 0; t < NT; t++) {
        int cur = t & 1;
        if (t + 1 < NT) {
            int kg = (t + 1) * 64;
            for (int i = tid; i < 2048; i += 256) {
                int row = i >> 4, c4 = (i & 15) << 2;
                cpa16(as_[cur ^ 1] + row * 68 + c4,
                      Ap + (size_t)(m0 + row) * DD + kg + c4);
                cpa16(bs_[cur ^ 1] + row * 68 + c4,
                      Bp + (size_t)(o0 + row) * DD + kg + c4);
            }
            CPA_COMMIT();
            CPA_WAIT1();
        } else {
            CPA_WAIT0();
        }
        __syncthreads();
        unsigned* A = as_[cur];
        unsigned* B = bs_[cur];
#pragma unroll
        for (int k0 = 0; k0 < 64; k0 += 8) {
            unsigned a[4][4], b[4][2];
#pragma unroll
            for (int mt = 0; mt < 4; mt++) {
                int rb = wm * 64 + mt * 16 + gi;
                a[mt][0] = A[rb * 68 + k0 + qi];
                a[mt][1] = A[(rb + 8) * 68 + k0 + qi];
                a[mt][2] = A[rb * 68 + k0 + 4 + qi];
                a[mt][3] = A[(rb + 8) * 68 + k0 + 4 + qi];
            }
#pragma unroll
            for (int nt = 0; nt < 4; nt++) {
                int nb = wn * 32 + nt * 8 + gi;
                b[nt][0] = B[nb * 68 + k0 + qi];
                b[nt][1] = B[nb * 68 + k0 + 4 + qi];
            }
#pragma unroll
            for (int mt = 0; mt < 4; mt++)
#pragma unroll
                for (int nt = 0; nt < 4; nt++)
                    mma8(acc[mt][nt], a[mt], b[nt]);
        }
        __syncthreads();
    }
#pragma unroll
    for (int mt = 0; mt < 4; mt++) {
        int r0 = m0 + wm * 64 + mt * 16 + gi;
#pragma unroll
        for (int nt = 0; nt < 4; nt++) {
            int c0 = o0 + wn * 32 + nt * 8 + 2 * qi;
            float b0 = bias[c0], b1 = bias[c0 + 1];
            out[(size_t)r0 * DD + c0]           = acc[mt][nt][0] + b0;
            out[(size_t)r0 * DD + c0 + 1]       = acc[mt][nt][1] + b1;
            out[(size_t)(r0 + 8) * DD + c0]     = acc[mt][nt][2] + b0;
            out[(size_t)(r0 + 8) * DD + c0 + 1] = acc[mt][nt][3] + b1;
        }
    }
}

// ---------------- launch ----------------------------------------------------
extern "C" void kernel_launch(void* const* d_in, const int* in_sizes, int n_in,
                              void* d_out, int out_size) {
    const float* values = (const float*)d_in[0];
    const float* keys   = (const float*)d_in[1];
    const float* query  = (const float*)d_in[2];
    const float* ovals  = (const float*)d_in[3];
    const float* okeys  = (const float*)d_in[4];
    const float* Wv     = (const float*)d_in[5];
    const float* Wk     = (const float*)d_in[6];
    const float* Wq     = (const float*)d_in[7];
    const float* fcw    = (const float*)d_in[8];
    const float* fcb    = (const float*)d_in[9];
    float* out = (float*)d_out;

    const int SMEM_QK = 3 * 128 * 68 * 4 + 2048;          // 106496
    const int SMEM_FC = 4 * 128 * 68 * 4;                 // 139264
    const int SMEM_PJ = (2 * 128 + 2 * 64) * 68 * 4;      // 104448
    cudaFuncSetAttribute(proj_tc_kernel,
        cudaFuncAttributeMaxDynamicSharedMemorySize, SMEM_PJ);
    cudaFuncSetAttribute(qkA_kernel,
        cudaFuncAttributeMaxDynamicSharedMemorySize, SMEM_QK);
    cudaFuncSetAttribute(qkB_kernel,
        cudaFuncAttributeMaxDynamicSharedMemorySize, SMEM_QK);
    cudaFuncSetAttribute(fc_tc_kernel,
        cudaFuncAttributeMaxDynamicSharedMemorySize, SMEM_FC);

    proj_tc_kernel<<<dim3(512, 5), 256, SMEM_PJ>>>(
        query, keys, values, okeys, ovals, Wq, Wk, Wv);
    wcvt_kernel<<<DD * DD / 256, 256>>>(fcw);
    diag_kernel<<<NROW / 8, 256>>>();
    qkA_kernel<<<dim3(QTILES, NHTOT), 256, SMEM_QK>>>();
    qkB_kernel<<<dim3(QTILES, NHTOT), 256, SMEM_QK>>>();
    reduceB_kernel<<<NROW / 256, 256>>>();
    pre_kernel<<<NB * LL * DD / 256, 256>>>();
    fc_tc_kernel<<<dim3(DD / 128, NB * LL / 128), 256, SMEM_FC>>>(fcb, out);
}

// round 15
// speedup vs baseline: 1.0440x; 1.0440x over previous
#include <cuda_runtime.h>
#include <cuda_fp16.h>

// Problem constants
#define NB   2
#define LL   2048
#define DD   1024
#define DH   64
#define NHTOT 32            // NB*HH
#define NROW 65536          // NHTOT*LL
#define QTILES 16           // LL/128

// (1/sqrt(D)) * log2(e): energies pre-scaled into base-2 domain
#define CSCALE 0.04508422002778f

// ---------------- scratch (static device allocations; no cudaMalloc) -------
static __device__ float  g_q [NROW*DH];     // tf32-rounded, pre-scaled by CSCALE
static __device__ float  g_k [NROW*DH];     // tf32-rounded
static __device__ float  g_v [NROW*DH];     // fp32 accurate
static __device__ float  g_ok[NROW*DH];     // tf32-rounded
static __device__ float  g_ov[NROW*DH];     // fp32 accurate
static __device__ float  g_de[NROW];        // diag energies (base-2 domain)
static __device__ float  g_rs[NROW];        // 1 / row softmax denom
static __device__ float  g_dp[NROW];        // diag probability
static __device__ float  g_cs[NROW];        // column sums of off-diag probs
static __device__ float  g_part[8*NROW];    // per-qslice column partials
static __device__ float  g_pre[NB*LL*DD];   // pre-fc activations (tf32-rounded)
static __device__ float  g_fcwt[DD*DD];     // fc weights (tf32-rounded)
static __device__ __half g_p[(size_t)NHTOT*LL*LL];  // unnormalized probs 2^e

// MUFU.EX2 (fast exp2 on the MUFU pipe)
__device__ __forceinline__ float ex2(float x) {
    float r;
    asm("ex2.approx.ftz.f32 %0, %1;" : "=f"(r) : "f"(x));
    return r;
}

__device__ __forceinline__ unsigned f2tf(float x) {
    unsigned r;
    asm("cvt.rna.tf32.f32 %0, %1;" : "=r"(r) : "f"(x));
    return r;
}

__device__ __forceinline__ void mma8(float c[4], const unsigned a[4],
                                     const unsigned b[2]) {
    asm volatile(
        "mma.sync.aligned.m16n8k8.row.col.f32.tf32.tf32.f32 "
        "{%0,%1,%2,%3}, {%4,%5,%6,%7}, {%8,%9}, {%0,%1,%2,%3};\n"
        : "+f"(c[0]), "+f"(c[1]), "+f"(c[2]), "+f"(c[3])
        : "r"(a[0]), "r"(a[1]), "r"(a[2]), "r"(a[3]), "r"(b[0]), "r"(b[1]));
}

__device__ __forceinline__ void cpa16(unsigned* dst, const unsigned* src) {
    unsigned d = (unsigned)__cvta_generic_to_shared(dst);
    asm volatile("cp.async.ca.shared.global [%0], [%1], 16;" :: "r"(d), "l"(src));
}
#define CPA_COMMIT() asm volatile("cp.async.commit_group;")
#define CPA_WAIT1()  asm volatile("cp.async.wait_group 1;")
#define CPA_WAIT0()  asm volatile("cp.async.wait_group 0;")

// ---------------- K1: fused tensor-core projections ------------------------
__global__ __launch_bounds__(256) void proj_tc_kernel(
        const float* __restrict__ xq, const float* __restrict__ xk,
        const float* __restrict__ xv, const float* __restrict__ xok,
        const float* __restrict__ xov,
        const float* __restrict__ Wq, const float* __restrict__ Wk,
        const float* __restrict__ Wv) {
    extern __shared__ __align__(16) unsigned shm[];
    unsigned* xh = shm;                 // [128][68]
    unsigned* xl = shm + 128 * 68;      // [128][68] (split only)
    unsigned* Wh = xl + 128 * 68;       // [64][68]
    unsigned* Wl = Wh + 64 * 68;        // [64][68]
    int sel = blockIdx.y;
    const float* x; const float* W; float* out;
    bool split = (sel >= 3);
    switch (sel) {
        case 0: x = xq;  W = Wq; out = g_q;  break;
        case 1: x = xk;  W = Wk; out = g_k;  break;
        case 2: x = xok; W = Wk; out = g_ok; break;
        case 3: x = xv;  W = Wv; out = g_v;  break;
        default: x = xov; W = Wv; out = g_ov; break;
    }
    int tid = threadIdx.x;
    int r0 = blockIdx.x << 7;
    for (int i = tid; i < 4096; i += 256) {
        int n = i >> 6, k = i & 63;
        float w = W[i];
        unsigned hi = f2tf(w);
        Wh[n * 68 + k] = hi;
        if (split) Wl[n * 68 + k] = f2tf(w - __uint_as_float(hi));
    }
    for (int i = tid; i < 2048; i += 256) {
        int row = i >> 4, c4 = (i & 15) << 2;
        float4 v = *(const float4*)(x + (size_t)(r0 + row) * DH + c4);
        unsigned* d = xh + row * 68 + c4;
        unsigned h0 = f2tf(v.x), h1 = f2tf(v.y), h2 = f2tf(v.z), h3 = f2tf(v.w);
        d[0] = h0; d[1] = h1; d[2] = h2; d[3] = h3;
        if (split) {
            unsigned* dl = xl + row * 68 + c4;
            dl[0] = f2tf(v.x - __uint_as_float(h0));
            dl[1] = f2tf(v.y - __uint_as_float(h1));
            dl[2] = f2tf(v.z - __uint_as_float(h2));
            dl[3] = f2tf(v.w - __uint_as_float(h3));
        }
    }
    __syncthreads();
    int lane = tid & 31, wid = tid >> 5;
    int wm = wid >> 1, wn = wid & 1;
    int gi = lane >> 2, qi = lane & 3;
    float acc[2][4][4];
#pragma unroll
    for (int mt = 0; mt < 2; mt++)
#pragma unroll
        for (int nt = 0; nt < 4; nt++)
#pragma unroll
            for (int e = 0; e < 4; e++) acc[mt][nt][e] = 0.0f;
#pragma unroll
    for (int k0 = 0; k0 < DH; k0 += 8) {
        unsigned a[2][4], b[4][2];
#pragma unroll
        for (int mt = 0; mt < 2; mt++) {
            int rb = wm * 32 + mt * 16 + gi;
            a[mt][0] = xh[rb * 68 + k0 + qi];
            a[mt][1] = xh[(rb + 8) * 68 + k0 + qi];
            a[mt][2] = xh[rb * 68 + k0 + 4 + qi];
            a[mt][3] = xh[(rb + 8) * 68 + k0 + 4 + qi];
        }
#pragma unroll
        for (int nt = 0; nt < 4; nt++) {
            int nb = wn * 32 + nt * 8 + gi;
            b[nt][0] = Wh[nb * 68 + k0 + qi];
            b[nt][1] = Wh[nb * 68 + k0 + 4 + qi];
        }
#pragma unroll
        for (int mt = 0; mt < 2; mt++)
#pragma unroll
            for (int nt = 0; nt < 4; nt++)
                mma8(acc[mt][nt], a[mt], b[nt]);
        if (split) {
            unsigned al[2][4], bl[4][2];
#pragma unroll
            for (int mt = 0; mt < 2; mt++) {
                int rb = wm * 32 + mt * 16 + gi;
                al[mt][0] = xl[rb * 68 + k0 + qi];
                al[mt][1] = xl[(rb + 8) * 68 + k0 + qi];
                al[mt][2] = xl[rb * 68 + k0 + 4 + qi];
                al[mt][3] = xl[(rb + 8) * 68 + k0 + 4 + qi];
            }
#pragma unroll
            for (int nt = 0; nt < 4; nt++) {
                int nb = wn * 32 + nt * 8 + gi;
                bl[nt][0] = Wl[nb * 68 + k0 + qi];
                bl[nt][1] = Wl[nb * 68 + k0 + 4 + qi];
            }
#pragma unroll
            for (int mt = 0; mt < 2; mt++)
#pragma unroll
                for (int nt = 0; nt < 4; nt++) {
                    mma8(acc[mt][nt], a[mt], bl[nt]);
                    mma8(acc[mt][nt], al[mt], b[nt]);
                }
        }
    }
    float oscale = (sel == 0) ? CSCALE : 1.0f;
    bool rnd = (sel < 3);
#pragma unroll
    for (int mt = 0; mt < 2; mt++) {
#pragma unroll
        for (int half = 0; half < 2; half++) {
            int row = r0 + wm * 32 + mt * 16 + gi + half * 8;
            int n = row >> 15;
            int l = (row >> 4) & (LL - 1);
            int h = row & 15;
            size_t obase = ((size_t)((n << 4) + h) * LL + l) * DH;
#pragma unroll
            for (int nt = 0; nt < 4; nt++) {
                int c = wn * 32 + nt * 8 + 2 * qi;
                float v0 = acc[mt][nt][half * 2 + 0] * oscale;
                float v1 = acc[mt][nt][half * 2 + 1] * oscale;
                if (rnd) {
                    v0 = __uint_as_float(f2tf(v0));
                    v1 = __uint_as_float(f2tf(v1));
                }
                out[obase + c] = v0;
                out[obase + c + 1] = v1;
            }
        }
    }
}

// ---------------- K2a: diagonal energies q.k (one warp per row) ------------
__global__ void diag_kernel() {
    int g = blockIdx.x * 256 + threadIdx.x;
    int w = g >> 5, lane = g & 31;
    const float* qp = g_q + (size_t)w * DH;
    const float* kp = g_k + (size_t)w * DH;
    float a = qp[lane] * kp[lane] + qp[lane + 32] * kp[lane + 32];
#pragma unroll
    for (int o = 16; o; o >>= 1) a += __shfl_xor_sync(0xffffffffu, a, o);
    if (lane == 0) g_de[w] = a;
}

// ------ shared tile-MMA body (reads qs, cur into acc) -----------------------
#define QK_MMA(qs, cur, acc)                                                  \
    _Pragma("unroll")                                                         \
    for (int k0 = 0; k0 < DH; k0 += 8) {                                      \
        unsigned a[4][4], b[4][2];                                            \
        _Pragma("unroll")                                                     \
        for (int mt = 0; mt < 4; mt++) {                                      \
            int rb = wm * 64 + mt * 16 + gi;                                  \
            a[mt][0] = qs[rb * 68 + k0 + qi];                                 \
            a[mt][1] = qs[(rb + 8) * 68 + k0 + qi];                           \
            a[mt][2] = qs[rb * 68 + k0 + 4 + qi];                             \
            a[mt][3] = qs[(rb + 8) * 68 + k0 + 4 + qi];                       \
        }                                                                     \
        _Pragma("unroll")                                                     \
        for (int nt = 0; nt < 4; nt++) {                                      \
            int nb = wn * 32 + nt * 8 + gi;                                   \
            b[nt][0] = cur[nb * 68 + k0 + qi];                                \
            b[nt][1] = cur[nb * 68 + k0 + 4 + qi];                            \
        }                                                                     \
        _Pragma("unroll")                                                     \
        for (int mt = 0; mt < 4; mt++)                                        \
            _Pragma("unroll")                                                 \
            for (int nt = 0; nt < 4; nt++)                                    \
                mma8(acc[mt][nt], a[mt], b[nt]);                              \
    }

// ---------------- K2: single MMA pass -> fp16 P + exact row sums -----------
// cp.async double-buffered ok tiles; dedicated fp16 staging buffer.
__global__ __launch_bounds__(256) void qk_tc_kernel() {
    extern __shared__ unsigned sh[];
    unsigned* qs  = sh;                    // [128][68]
    unsigned* os0 = sh + 128 * 68;         // [128][68] double buffer
    unsigned* os1 = os0 + 128 * 68;
    __half*  ps  = (__half*)(os1 + 128 * 68);  // [128][136]
    int nh = blockIdx.y;
    int qt = (QTILES - 1) - blockIdx.x;    // heavy blocks first
    int q0 = qt << 7;
    const unsigned* qb = (const unsigned*)g_q + (size_t)nh * LL * DH;
    const unsigned* ob = (const unsigned*)g_ok + (size_t)nh * LL * DH;
    __half* Pp = g_p + (size_t)nh * LL * LL;
    int tid = threadIdx.x;
    int lane = tid & 31, wid = tid >> 5;
    int wm = wid >> 2, wn = wid & 3;
    int gi = lane >> 2, qi = lane & 3;

    for (int i = tid; i < 2048; i += 256) {
        int row = i >> 4, c4 = (i & 15) << 2;
        cpa16(qs + row * 68 + c4, qb + (size_t)(q0 + row) * DH + c4);
        cpa16(os0 + row * 68 + c4, ob + (size_t)row * DH + c4);
    }
    CPA_COMMIT();
    float s[8];
#pragma unroll
    for (int i = 0; i < 8; i++) s[i] = 0.0f;
    int ntile = qt + 1;
    for (int t = 0; t < ntile; t++) {
        unsigned* cur = (t & 1) ? os1 : os0;
        unsigned* nxt = (t & 1) ? os0 : os1;
        if (t + 1 < ntile) {
            for (int i = tid; i < 2048; i += 256) {
                int row = i >> 4, c4 = (i & 15) << 2;
                cpa16(nxt + row * 68 + c4,
                      ob + (size_t)((t + 1) * 128 + row) * DH + c4);
            }
            CPA_COMMIT();
            CPA_WAIT1();
        } else {
            CPA_WAIT0();
        }
        __syncthreads();   // cur visible; prev store-loop done (ps reusable)
        float acc[4][4][4];
#pragma unroll
        for (int mt = 0; mt < 4; mt++)
#pragma unroll
            for (int nt = 0; nt < 4; nt++)
#pragma unroll
                for (int e = 0; e < 4; e++) acc[mt][nt][e] = 0.0f;
        QK_MMA(qs, cur, acc)
        bool dt = (t == ntile - 1);
#pragma unroll
        for (int mt = 0; mt < 4; mt++) {
            int rl = wm * 64 + mt * 16 + gi;
#pragma unroll
            for (int nt = 0; nt < 4; nt++) {
                int cl = wn * 32 + nt * 8 + 2 * qi;
                float u0 = ex2(acc[mt][nt][0]);
                float u1 = ex2(acc[mt][nt][1]);
                float u2 = ex2(acc[mt][nt][2]);
                float u3 = ex2(acc[mt][nt][3]);
                if (dt) {   // causal + diagonal excluded (local coords)
                    if (cl     >= rl)     u0 = 0.0f;
                    if (cl + 1 >= rl)     u1 = 0.0f;
                    if (cl     >= rl + 8) u2 = 0.0f;
                    if (cl + 1 >= rl + 8) u3 = 0.0f;
                }
                s[mt * 2 + 0] += u0 + u1;
                s[mt * 2 + 1] += u2 + u3;
                *(__half2*)(ps + rl * 136 + cl)       = __floats2half2_rn(u0, u1);
                *(__half2*)(ps + (rl + 8) * 136 + cl) = __floats2half2_rn(u2, u3);
            }
        }
        __syncthreads();   // ps complete; all warps done reading cur
        for (int i = tid; i < 2048; i += 256) {
            int row = i >> 4, c8 = (i & 15) << 3;
            *(float4*)(Pp + (size_t)(q0 + row) * LL + t * 128 + c8) =
                *(const float4*)(ps + row * 136 + c8);
        }
    }
#pragma unroll
    for (int i = 0; i < 8; i++) {
        s[i] += __shfl_xor_sync(0xffffffffu, s[i], 1);
        s[i] += __shfl_xor_sync(0xffffffffu, s[i], 2);
    }
    __syncthreads();
    float* red = (float*)ps;           // [128][4]
    if (qi == 0) {
#pragma unroll
        for (int mt = 0; mt < 4; mt++) {
            int rl = wm * 64 + mt * 16 + gi;
            red[rl * 4 + wn] = s[mt * 2 + 0];
            red[(rl + 8) * 4 + wn] = s[mt * 2 + 1];
        }
    }
    __syncthreads();
    if (tid < 128) {
        float tot = red[tid * 4] + red[tid * 4 + 1] +
                    red[tid * 4 + 2] + red[tid * 4 + 3];
        int row = nh * LL + q0 + tid;
        float ud = ex2(g_de[row]);       // already base-2 scaled
        float rinv = 1.0f / (tot + ud);
        g_rs[row] = rinv;
        g_dp[row] = ud * rinv;
    }
}

// ---------------- K3: column partial sums (lower triangle only) ------------
__global__ void colsum2_kernel() {
    int nh = blockIdx.y;
    int l0 = blockIdx.x << 7;              // 16 column tiles of 128
    int qz = blockIdx.z;                   // 4 q-chunks of 512
    int tid = threadIdx.x;
    int l = l0 + (tid & 127);
    int sub = tid >> 7;                    // split each chunk in 2
    int qs0 = (qz << 9) + (sub << 8);
    const __half* Pp = g_p + (size_t)nh * LL * LL;
    const float* rs = g_rs + nh * LL;
    float sum = 0.0f;
    int qstart = (l > qs0) ? l : qs0;
#pragma unroll 8
    for (int q = qstart; q < qs0 + 256; q++) {
        float pv = __half2float(__ldg(Pp + (size_t)q * LL + l));
        sum += pv * __ldg(rs + q);
    }
    int slice = (qz << 1) + sub;           // 0..7
    g_part[((size_t)slice * NHTOT + nh) * LL + l] = sum;
}

// ---------------- K3b: reduce 8 partials ----------------------------------
__global__ void reduce2_kernel() {
    int idx = blockIdx.x * 256 + threadIdx.x;   // < NROW
    int nh = idx >> 11;
    int l = idx & (LL - 1);
    float sum = 0.0f;
#pragma unroll
    for (int sl = 0; sl < 8; sl++)
        sum += g_part[((size_t)sl * NHTOT + nh) * LL + l];
    g_cs[idx] = sum;
}

// ---------------- K4a: pre = diag*v + colsum*ov (tf32-rounded) -------------
__global__ void pre_kernel() {
    int idx = blockIdx.x * 256 + threadIdx.x;   // < NB*LL*DD
    int d = idx & 63;
    int h = (idx >> 6) & 15;
    int l = (idx >> 10) & (LL - 1);
    int n = idx >> 21;
    int r = ((n << 4) + h) * LL + l;
    size_t b = (size_t)r * DH + d;
    float v = g_dp[r] * g_v[b] + g_cs[r] * g_ov[b];
    g_pre[idx] = __uint_as_float(f2tf(v));
}

// ---------------- K4a': fc weight -> tf32 bits ------------------------------
__global__ void wcvt_kernel(const float* __restrict__ w) {
    int i = blockIdx.x * 256 + threadIdx.x;
    g_fcwt[i] = __uint_as_float(f2tf(w[i]));
}

// ---------------- K4b: out = pre @ fc_w^T + fc_b (tensor core, 2-buf) ------
__global__ __launch_bounds__(256) void fc_tc_kernel(
        const float* __restrict__ bias, float* __restrict__ out) {
    extern __shared__ unsigned sh[];
    unsigned* as_[2] = { sh, sh + 128 * 68 };
    unsigned* bs_[2] = { sh + 2 * 128 * 68, sh + 3 * 128 * 68 };
    const unsigned* Ap = (const unsigned*)g_pre;
    const unsigned* Bp = (const unsigned*)g_fcwt;
    int m0 = blockIdx.y << 7, o0 = blockIdx.x << 7;
    int tid = threadIdx.x;
    int lane = tid & 31, wid = tid >> 5;
    int wm = wid >> 2, wn = wid & 3;
    int gi = lane >> 2, qi = lane & 3;
    float acc[4][4][4];
#pragma unroll
    for (int mt = 0; mt < 4; mt++)
#pragma unroll
        for (int nt = 0; nt < 4; nt++)
#pragma unroll
            for (int e = 0; e < 4; e++) acc[mt][nt][e] = 0.0f;
    for (int i = tid; i < 2048; i += 256) {
        int row = i >> 4, c4 = (i & 15) << 2;
        cpa16(as_[0] + row * 68 + c4, Ap + (size_t)(m0 + row) * DD + c4);
        cpa16(bs_[0] + row * 68 + c4, Bp + (size_t)(o0 + row) * DD + c4);
    }
    CPA_COMMIT();
    const int NT = DD / 64;
    for (int t = 0; t < NT; t++) {
        int cur = t & 1;
        if (t + 1 < NT) {
            int kg = (t + 1) * 64;
            for (int i = tid; i < 2048; i += 256) {
                int row = i >> 4, c4 = (i & 15) << 2;
                cpa16(as_[cur ^ 1] + row * 68 + c4,
                      Ap + (size_t)(m0 + row) * DD + kg + c4);
                cpa16(bs_[cur ^ 1] + row * 68 + c4,
                      Bp + (size_t)(o0 + row) * DD + kg + c4);
            }
            CPA_COMMIT();
            CPA_WAIT1();
        } else {
            CPA_WAIT0();
        }
        __syncthreads();
        unsigned* A = as_[cur];
        unsigned* B = bs_[cur];
#pragma unroll
        for (int k0 = 0; k0 < 64; k0 += 8) {
            unsigned a[4][4], b[4][2];
#pragma unroll
            for (int mt = 0; mt < 4; mt++) {
                int rb = wm * 64 + mt * 16 + gi;
                a[mt][0] = A[rb * 68 + k0 + qi];
                a[mt][1] = A[(rb + 8) * 68 + k0 + qi];
                a[mt][2] = A[rb * 68 + k0 + 4 + qi];
                a[mt][3] = A[(rb + 8) * 68 + k0 + 4 + qi];
            }
#pragma unroll
            for (int nt = 0; nt < 4; nt++) {
                int nb = wn * 32 + nt * 8 + gi;
                b[nt][0] = B[nb * 68 + k0 + qi];
                b[nt][1] = B[nb * 68 + k0 + 4 + qi];
            }
#pragma unroll
            for (int mt = 0; mt < 4; mt++)
#pragma unroll
                for (int nt = 0; nt < 4; nt++)
                    mma8(acc[mt][nt], a[mt], b[nt]);
        }
        __syncthreads();
    }
#pragma unroll
    for (int mt = 0; mt < 4; mt++) {
        int r0 = m0 + wm * 64 + mt * 16 + gi;
#pragma unroll
        for (int nt = 0; nt < 4; nt++) {
            int c0 = o0 + wn * 32 + nt * 8 + 2 * qi;
            float b0 = bias[c0], b1 = bias[c0 + 1];
            out[(size_t)r0 * DD + c0]           = acc[mt][nt][0] + b0;
            out[(size_t)r0 * DD + c0 + 1]       = acc[mt][nt][1] + b1;
            out[(size_t)(r0 + 8) * DD + c0]     = acc[mt][nt][2] + b0;
            out[(size_t)(r0 + 8) * DD + c0 + 1] = acc[mt][nt][3] + b1;
        }
    }
}

// ---------------- launch ----------------------------------------------------
extern "C" void kernel_launch(void* const* d_in, const int* in_sizes, int n_in,
                              void* d_out, int out_size) {
    const float* values = (const float*)d_in[0];
    const float* keys   = (const float*)d_in[1];
    const float* query  = (const float*)d_in[2];
    const float* ovals  = (const float*)d_in[3];
    const float* okeys  = (const float*)d_in[4];
    const float* Wv     = (const float*)d_in[5];
    const float* Wk     = (const float*)d_in[6];
    const float* Wq     = (const float*)d_in[7];
    const float* fcw    = (const float*)d_in[8];
    const float* fcb    = (const float*)d_in[9];
    float* out = (float*)d_out;

    const int SMEM_QK = 3 * 128 * 68 * 4 + 128 * 136 * 2; // 139264
    const int SMEM_FC = 4 * 128 * 68 * 4;                 // 139264
    const int SMEM_PJ = (2 * 128 + 2 * 64) * 68 * 4;      // 104448
    cudaFuncSetAttribute(proj_tc_kernel,
        cudaFuncAttributeMaxDynamicSharedMemorySize, SMEM_PJ);
    cudaFuncSetAttribute(qk_tc_kernel,
        cudaFuncAttributeMaxDynamicSharedMemorySize, SMEM_QK);
    cudaFuncSetAttribute(fc_tc_kernel,
        cudaFuncAttributeMaxDynamicSharedMemorySize, SMEM_FC);

    proj_tc_kernel<<<dim3(512, 5), 256, SMEM_PJ>>>(
        query, keys, values, okeys, ovals, Wq, Wk, Wv);
    wcvt_kernel<<<DD * DD / 256, 256>>>(fcw);
    diag_kernel<<<NROW / 8, 256>>>();
    qk_tc_kernel<<<dim3(QTILES, NHTOT), 256, SMEM_QK>>>();
    colsum2_kernel<<<dim3(16, NHTOT, 4), 256>>>();
    reduce2_kernel<<<NROW / 256, 256>>>();
    pre_kernel<<<NB * LL * DD / 256, 256>>>();
    fc_tc_kernel<<<dim3(DD / 128, NB * LL / 128), 256, SMEM_FC>>>(fcb, out);
}

// round 16
// speedup vs baseline: 1.1627x; 1.1137x over previous
#include <cuda_runtime.h>
#include <cuda_fp16.h>

// Problem constants
#define NB   2
#define LL   2048
#define DD   1024
#define DH   64
#define NHTOT 32            // NB*HH
#define NROW 65536          // NHTOT*LL
#define QTILES 16           // LL/128

// (1/sqrt(D)) * log2(e): energies pre-scaled into base-2 domain
#define CSCALE 0.04508422002778f

// ---------------- scratch (static device allocations; no cudaMalloc) -------
static __device__ __half g_qh[NROW*DH];     // fp16, pre-scaled by CSCALE
static __device__ __half g_kh[NROW*DH];     // fp16
static __device__ __half g_okh[NROW*DH];    // fp16
static __device__ float  g_v [NROW*DH];     // fp32 accurate
static __device__ float  g_ov[NROW*DH];     // fp32 accurate
static __device__ float  g_de[NROW];        // diag energies (base-2 domain)
static __device__ float  g_rs[NROW];        // 1 / row softmax denom
static __device__ float  g_dp[NROW];        // diag probability
static __device__ float  g_cs[NROW];        // column sums of off-diag probs
static __device__ float  g_part[8*NROW];    // per-qslice column partials
static __device__ float  g_pre[NB*LL*DD];   // pre-fc activations (tf32-rounded)
static __device__ float  g_fcwt[DD*DD];     // fc weights (tf32-rounded)
static __device__ __half g_p[(size_t)NHTOT*LL*LL];  // unnormalized probs 2^e

// MUFU.EX2 (fast exp2 on the MUFU pipe)
__device__ __forceinline__ float ex2(float x) {
    float r;
    asm("ex2.approx.ftz.f32 %0, %1;" : "=f"(r) : "f"(x));
    return r;
}

__device__ __forceinline__ unsigned f2tf(float x) {
    unsigned r;
    asm("cvt.rna.tf32.f32 %0, %1;" : "=r"(r) : "f"(x));
    return r;
}

// tf32 m16n8k8 (projections / fc)
__device__ __forceinline__ void mma8(float c[4], const unsigned a[4],
                                     const unsigned b[2]) {
    asm volatile(
        "mma.sync.aligned.m16n8k8.row.col.f32.tf32.tf32.f32 "
        "{%0,%1,%2,%3}, {%4,%5,%6,%7}, {%8,%9}, {%0,%1,%2,%3};\n"
        : "+f"(c[0]), "+f"(c[1]), "+f"(c[2]), "+f"(c[3])
        : "r"(a[0]), "r"(a[1]), "r"(a[2]), "r"(a[3]), "r"(b[0]), "r"(b[1]));
}

// fp16 m16n8k16 with fp32 accum (qk energies)
__device__ __forceinline__ void mma16f(float c[4], const unsigned a[4],
                                       const unsigned b[2]) {
    asm volatile(
        "mma.sync.aligned.m16n8k16.row.col.f32.f16.f16.f32 "
        "{%0,%1,%2,%3}, {%4,%5,%6,%7}, {%8,%9}, {%0,%1,%2,%3};\n"
        : "+f"(c[0]), "+f"(c[1]), "+f"(c[2]), "+f"(c[3])
        : "r"(a[0]), "r"(a[1]), "r"(a[2]), "r"(a[3]), "r"(b[0]), "r"(b[1]));
}

__device__ __forceinline__ void cpa16(void* dst, const void* src) {
    unsigned d = (unsigned)__cvta_generic_to_shared(dst);
    asm volatile("cp.async.ca.shared.global [%0], [%1], 16;" :: "r"(d), "l"(src));
}
#define CPA_COMMIT() asm volatile("cp.async.commit_group;")
#define CPA_WAIT1()  asm volatile("cp.async.wait_group 1;")
#define CPA_WAIT0()  asm volatile("cp.async.wait_group 0;")

// ---------------- K1: fused tensor-core projections ------------------------
// sel 0..2 -> fp16 outputs (q pre-scaled, k, ok); sel 3..4 -> fp32 (v, ov).
__global__ __launch_bounds__(256) void proj_tc_kernel(
        const float* __restrict__ xq, const float* __restrict__ xk,
        const float* __restrict__ xv, const float* __restrict__ xok,
        const float* __restrict__ xov,
        const float* __restrict__ Wq, const float* __restrict__ Wk,
        const float* __restrict__ Wv) {
    extern __shared__ __align__(16) unsigned shm[];
    unsigned* xh = shm;                 // [128][68]
    unsigned* xl = shm + 128 * 68;      // [128][68] (split only)
    unsigned* Wh = xl + 128 * 68;       // [64][68]
    unsigned* Wl = Wh + 64 * 68;        // [64][68]
    int sel = blockIdx.y;
    const float* x; const float* W;
    __half* outh = 0; float* outf = 0;
    bool split = (sel >= 3);
    switch (sel) {
        case 0: x = xq;  W = Wq; outh = g_qh;  break;
        case 1: x = xk;  W = Wk; outh = g_kh;  break;
        case 2: x = xok; W = Wk; outh = g_okh; break;
        case 3: x = xv;  W = Wv; outf = g_v;   break;
        default: x = xov; W = Wv; outf = g_ov; break;
    }
    int tid = threadIdx.x;
    int r0 = blockIdx.x << 7;
    for (int i = tid; i < 4096; i += 256) {
        int n = i >> 6, k = i & 63;
        float w = W[i];
        unsigned hi = f2tf(w);
        Wh[n * 68 + k] = hi;
        if (split) Wl[n * 68 + k] = f2tf(w - __uint_as_float(hi));
    }
    for (int i = tid; i < 2048; i += 256) {
        int row = i >> 4, c4 = (i & 15) << 2;
        float4 v = *(const float4*)(x + (size_t)(r0 + row) * DH + c4);
        unsigned* d = xh + row * 68 + c4;
        unsigned h0 = f2tf(v.x), h1 = f2tf(v.y), h2 = f2tf(v.z), h3 = f2tf(v.w);
        d[0] = h0; d[1] = h1; d[2] = h2; d[3] = h3;
        if (split) {
            unsigned* dl = xl + row * 68 + c4;
            dl[0] = f2tf(v.x - __uint_as_float(h0));
            dl[1] = f2tf(v.y - __uint_as_float(h1));
            dl[2] = f2tf(v.z - __uint_as_float(h2));
            dl[3] = f2tf(v.w - __uint_as_float(h3));
        }
    }
    __syncthreads();
    int lane = tid & 31, wid = tid >> 5;
    int wm = wid >> 1, wn = wid & 1;
    int gi = lane >> 2, qi = lane & 3;
    float acc[2][4][4];
#pragma unroll
    for (int mt = 0; mt < 2; mt++)
#pragma unroll
        for (int nt = 0; nt < 4; nt++)
#pragma unroll
            for (int e = 0; e < 4; e++) acc[mt][nt][e] = 0.0f;
#pragma unroll
    for (int k0 = 0; k0 < DH; k0 += 8) {
        unsigned a[2][4], b[4][2];
#pragma unroll
        for (int mt = 0; mt < 2; mt++) {
            int rb = wm * 32 + mt * 16 + gi;
            a[mt][0] = xh[rb * 68 + k0 + qi];
            a[mt][1] = xh[(rb + 8) * 68 + k0 + qi];
            a[mt][2] = xh[rb * 68 + k0 + 4 + qi];
            a[mt][3] = xh[(rb + 8) * 68 + k0 + 4 + qi];
        }
#pragma unroll
        for (int nt = 0; nt < 4; nt++) {
            int nb = wn * 32 + nt * 8 + gi;
            b[nt][0] = Wh[nb * 68 + k0 + qi];
            b[nt][1] = Wh[nb * 68 + k0 + 4 + qi];
        }
#pragma unroll
        for (int mt = 0; mt < 2; mt++)
#pragma unroll
            for (int nt = 0; nt < 4; nt++)
                mma8(acc[mt][nt], a[mt], b[nt]);
        if (split) {
            unsigned al[2][4], bl[4][2];
#pragma unroll
            for (int mt = 0; mt < 2; mt++) {
                int rb = wm * 32 + mt * 16 + gi;
                al[mt][0] = xl[rb * 68 + k0 + qi];
                al[mt][1] = xl[(rb + 8) * 68 + k0 + qi];
                al[mt][2] = xl[rb * 68 + k0 + 4 + qi];
                al[mt][3] = xl[(rb + 8) * 68 + k0 + 4 + qi];
            }
#pragma unroll
            for (int nt = 0; nt < 4; nt++) {
                int nb = wn * 32 + nt * 8 + gi;
                bl[nt][0] = Wl[nb * 68 + k0 + qi];
                bl[nt][1] = Wl[nb * 68 + k0 + 4 + qi];
            }
#pragma unroll
            for (int mt = 0; mt < 2; mt++)
#pragma unroll
                for (int nt = 0; nt < 4; nt++) {
                    mma8(acc[mt][nt], a[mt], bl[nt]);
                    mma8(acc[mt][nt], al[mt], b[nt]);
                }
        }
    }
    float oscale = (sel == 0) ? CSCALE : 1.0f;
#pragma unroll
    for (int mt = 0; mt < 2; mt++) {
#pragma unroll
        for (int half = 0; half < 2; half++) {
            int row = r0 + wm * 32 + mt * 16 + gi + half * 8;
            int n = row >> 15;
            int l = (row >> 4) & (LL - 1);
            int h = row & 15;
            size_t obase = ((size_t)((n << 4) + h) * LL + l) * DH;
#pragma unroll
            for (int nt = 0; nt < 4; nt++) {
                int c = wn * 32 + nt * 8 + 2 * qi;
                float v0 = acc[mt][nt][half * 2 + 0] * oscale;
                float v1 = acc[mt][nt][half * 2 + 1] * oscale;
                if (outh) {
                    *(__half2*)(outh + obase + c) = __floats2half2_rn(v0, v1);
                } else {
                    outf[obase + c] = v0;
                    outf[obase + c + 1] = v1;
                }
            }
        }
    }
}

// ---------------- K2a: diagonal energies q.k (one warp per row) ------------
__global__ void diag_kernel() {
    int g = blockIdx.x * 256 + threadIdx.x;
    int w = g >> 5, lane = g & 31;
    const __half* qp = g_qh + (size_t)w * DH;
    const __half* kp = g_kh + (size_t)w * DH;
    float a = __half2float(qp[lane]) * __half2float(kp[lane]) +
              __half2float(qp[lane + 32]) * __half2float(kp[lane + 32]);
#pragma unroll
    for (int o = 16; o; o >>= 1) a += __shfl_xor_sync(0xffffffffu, a, o);
    if (lane == 0) g_de[w] = a;
}

// ------ fp16 tile-MMA body (qs, cur are __half* tiles, stride 72) ----------
#define QK_MMA16(qs, cur, acc)                                                \
    _Pragma("unroll")                                                         \
    for (int k0 = 0; k0 < DH; k0 += 16) {                                     \
        unsigned a[4][4], b[4][2];                                            \
        _Pragma("unroll")                                                     \
        for (int mt = 0; mt < 4; mt++) {                                      \
            int rb = wm * 64 + mt * 16 + gi;                                  \
            a[mt][0] = *(const unsigned*)(qs + rb * 72 + k0 + 2 * qi);        \
            a[mt][1] = *(const unsigned*)(qs + (rb + 8) * 72 + k0 + 2 * qi);  \
            a[mt][2] = *(const unsigned*)(qs + rb * 72 + k0 + 8 + 2 * qi);    \
            a[mt][3] = *(const unsigned*)(qs + (rb + 8) * 72 + k0 + 8 + 2 * qi);\
        }                                                                     \
        _Pragma("unroll")                                                     \
        for (int nt = 0; nt < 4; nt++) {                                      \
            int nb = wn * 32 + nt * 8 + gi;                                   \
            b[nt][0] = *(const unsigned*)(cur + nb * 72 + k0 + 2 * qi);       \
            b[nt][1] = *(const unsigned*)(cur + nb * 72 + k0 + 8 + 2 * qi);   \
        }                                                                     \
        _Pragma("unroll")                                                     \
        for (int mt = 0; mt < 4; mt++)                                        \
            _Pragma("unroll")                                                 \
            for (int nt = 0; nt < 4; nt++)                                    \
                mma16f(acc[mt][nt], a[mt], b[nt]);                            \
    }

// ---------------- K2: fp16 MMA pass -> fp16 P + exact row sums -------------
__global__ __launch_bounds__(256) void qk_tc_kernel() {
    extern __shared__ __align__(16) __half shh[];
    __half* qs  = shh;                     // [128][72]
    __half* os0 = shh + 128 * 72;          // [128][72] double buffer
    __half* os1 = os0 + 128 * 72;
    __half* ps  = os1 + 128 * 72;          // [128][136]
    int nh = blockIdx.y;
    int qt = (QTILES - 1) - blockIdx.x;    // heavy blocks first
    int q0 = qt << 7;
    const __half* qb = g_qh + (size_t)nh * LL * DH;
    const __half* ob = g_okh + (size_t)nh * LL * DH;
    __half* Pp = g_p + (size_t)nh * LL * LL;
    int tid = threadIdx.x;
    int lane = tid & 31, wid = tid >> 5;
    int wm = wid >> 2, wn = wid & 3;
    int gi = lane >> 2, qi = lane & 3;

    // q tile + first ok tile (each row = 64 halves = 8 x 16B chunks)
    for (int i = tid; i < 1024; i += 256) {
        int row = i >> 3, c8 = (i & 7) << 3;
        cpa16(qs + row * 72 + c8, qb + (size_t)(q0 + row) * DH + c8);
        cpa16(os0 + row * 72 + c8, ob + (size_t)row * DH + c8);
    }
    CPA_COMMIT();
    float s[8];
#pragma unroll
    for (int i = 0; i < 8; i++) s[i] = 0.0f;
    int ntile = qt + 1;
    for (int t = 0; t < ntile; t++) {
        __half* cur = (t & 1) ? os1 : os0;
        __half* nxt = (t & 1) ? os0 : os1;
        if (t + 1 < ntile) {
            for (int i = tid; i < 1024; i += 256) {
                int row = i >> 3, c8 = (i & 7) << 3;
                cpa16(nxt + row * 72 + c8,
                      ob + (size_t)((t + 1) * 128 + row) * DH + c8);
            }
            CPA_COMMIT();
            CPA_WAIT1();
        } else {
            CPA_WAIT0();
        }
        __syncthreads();   // cur visible; prev store-loop done (ps reusable)
        float acc[4][4][4];
#pragma unroll
        for (int mt = 0; mt < 4; mt++)
#pragma unroll
            for (int nt = 0; nt < 4; nt++)
#pragma unroll
                for (int e = 0; e < 4; e++) acc[mt][nt][e] = 0.0f;
        QK_MMA16(qs, cur, acc)
        bool dt = (t == ntile - 1);
#pragma unroll
        for (int mt = 0; mt < 4; mt++) {
            int rl = wm * 64 + mt * 16 + gi;
#pragma unroll
            for (int nt = 0; nt < 4; nt++) {
                int cl = wn * 32 + nt * 8 + 2 * qi;
                float u0 = ex2(acc[mt][nt][0]);
                float u1 = ex2(acc[mt][nt][1]);
                float u2 = ex2(acc[mt][nt][2]);
                float u3 = ex2(acc[mt][nt][3]);
                if (dt) {   // causal + diagonal excluded (local coords)
                    if (cl     >= rl)     u0 = 0.0f;
                    if (cl + 1 >= rl)     u1 = 0.0f;
                    if (cl     >= rl + 8) u2 = 0.0f;
                    if (cl + 1 >= rl + 8) u3 = 0.0f;
                }
                s[mt * 2 + 0] += u0 + u1;
                s[mt * 2 + 1] += u2 + u3;
                *(__half2*)(ps + rl * 136 + cl)       = __floats2half2_rn(u0, u1);
                *(__half2*)(ps + (rl + 8) * 136 + cl) = __floats2half2_rn(u2, u3);
            }
        }
        __syncthreads();   // ps complete; all warps done reading cur
        for (int i = tid; i < 2048; i += 256) {
            int row = i >> 4, c8 = (i & 15) << 3;
            *(float4*)(Pp + (size_t)(q0 + row) * LL + t * 128 + c8) =
                *(const float4*)(ps + row * 136 + c8);
        }
    }
#pragma unroll
    for (int i = 0; i < 8; i++) {
        s[i] += __shfl_xor_sync(0xffffffffu, s[i], 1);
        s[i] += __shfl_xor_sync(0xffffffffu, s[i], 2);
    }
    __syncthreads();
    float* red = (float*)ps;           // [128][4]
    if (qi == 0) {
#pragma unroll
        for (int mt = 0; mt < 4; mt++) {
            int rl = wm * 64 + mt * 16 + gi;
            red[rl * 4 + wn] = s[mt * 2 + 0];
            red[(rl + 8) * 4 + wn] = s[mt * 2 + 1];
        }
    }
    __syncthreads();
    if (tid < 128) {
        float tot = red[tid * 4] + red[tid * 4 + 1] +
                    red[tid * 4 + 2] + red[tid * 4 + 3];
        int row = nh * LL + q0 + tid;
        float ud = ex2(g_de[row]);       // already base-2 scaled
        float rinv = 1.0f / (tot + ud);
        g_rs[row] = rinv;
        g_dp[row] = ud * rinv;
    }
}

// ---------------- K3: column partial sums (lower triangle only) ------------
__global__ void colsum2_kernel() {
    int nh = blockIdx.y;
    int l0 = blockIdx.x << 7;              // 16 column tiles of 128
    int qz = blockIdx.z;                   // 4 q-chunks of 512
    int tid = threadIdx.x;
    int l = l0 + (tid & 127);
    int sub = tid >> 7;                    // split each chunk in 2
    int qs0 = (qz << 9) + (sub << 8);
    const __half* Pp = g_p + (size_t)nh * LL * LL;
    const float* rs = g_rs + nh * LL;
    float sum = 0.0f;
    int qstart = (l > qs0) ? l : qs0;
#pragma unroll 8
    for (int q = qstart; q < qs0 + 256; q++) {
        float pv = __half2float(__ldg(Pp + (size_t)q * LL + l));
        sum += pv * __ldg(rs + q);
    }
    int slice = (qz << 1) + sub;           // 0..7
    g_part[((size_t)slice * NHTOT + nh) * LL + l] = sum;
}

// ---------------- K3b: reduce 8 partials ----------------------------------
__global__ void reduce2_kernel() {
    int idx = blockIdx.x * 256 + threadIdx.x;   // < NROW
    int nh = idx >> 11;
    int l = idx & (LL - 1);
    float sum = 0.0f;
#pragma unroll
    for (int sl = 0; sl < 8; sl++)
        sum += g_part[((size_t)sl * NHTOT + nh) * LL + l];
    g_cs[idx] = sum;
}

// ---------------- K4a: pre = diag*v + colsum*ov (tf32-rounded) -------------
__global__ void pre_kernel() {
    int idx = blockIdx.x * 256 + threadIdx.x;   // < NB*LL*DD
    int d = idx & 63;
    int h = (idx >> 6) & 15;
    int l = (idx >> 10) & (LL - 1);
    int n = idx >> 21;
    int r = ((n << 4) + h) * LL + l;
    size_t b = (size_t)r * DH + d;
    float v = g_dp[r] * g_v[b] + g_cs[r] * g_ov[b];
    g_pre[idx] = __uint_as_float(f2tf(v));
}

// ---------------- K4a': fc weight -> tf32 bits ------------------------------
__global__ void wcvt_kernel(const float* __restrict__ w) {
    int i = blockIdx.x * 256 + threadIdx.x;
    g_fcwt[i] = __uint_as_float(f2tf(w[i]));
}

// ---------------- K4b: out = pre @ fc_w^T + fc_b (tensor core, 2-buf) ------
__global__ __launch_bounds__(256) void fc_tc_kernel(
        const float* __restrict__ bias, float* __restrict__ out) {
    extern __shared__ unsigned sh[];
    unsigned* as_[2] = { sh, sh + 128 * 68 };
    unsigned* bs_[2] = { sh + 2 * 128 * 68, sh + 3 * 128 * 68 };
    const unsigned* Ap = (const unsigned*)g_pre;
    const unsigned* Bp = (const unsigned*)g_fcwt;
    int m0 = blockIdx.y << 7, o0 = blockIdx.x << 7;
    int tid = threadIdx.x;
    int lane = tid & 31, wid = tid >> 5;
    int wm = wid >> 2, wn = wid & 3;
    int gi = lane >> 2, qi = lane & 3;
    float acc[4][4][4];
#pragma unroll
    for (int mt = 0; mt < 4; mt++)
#pragma unroll
        for (int nt = 0; nt < 4; nt++)
#pragma unroll
            for (int e = 0; e < 4; e++) acc[mt][nt][e] = 0.0f;
    for (int i = tid; i < 2048; i += 256) {
        int row = i >> 4, c4 = (i & 15) << 2;
        cpa16(as_[0] + row * 68 + c4, Ap + (size_t)(m0 + row) * DD + c4);
        cpa16(bs_[0] + row * 68 + c4, Bp + (size_t)(o0 + row) * DD + c4);
    }
    CPA_COMMIT();
    const int NT = DD / 64;
    for (int t = 0; t < NT; t++) {
        int cur = t & 1;
        if (t + 1 < NT) {
            int kg = (t + 1) * 64;
            for (int i = tid; i < 2048; i += 256) {
                int row = i >> 4, c4 = (i & 15) << 2;
                cpa16(as_[cur ^ 1] + row * 68 + c4,
                      Ap + (size_t)(m0 + row) * DD + kg + c4);
                cpa16(bs_[cur ^ 1] + row * 68 + c4,
                      Bp + (size_t)(o0 + row) * DD + kg + c4);
            }
            CPA_COMMIT();
            CPA_WAIT1();
        } else {
            CPA_WAIT0();
        }
        __syncthreads();
        unsigned* A = as_[cur];
        unsigned* B = bs_[cur];
#pragma unroll
        for (int k0 = 0; k0 < 64; k0 += 8) {
            unsigned a[4][4], b[4][2];
#pragma unroll
            for (int mt = 0; mt < 4; mt++) {
                int rb = wm * 64 + mt * 16 + gi;
                a[mt][0] = A[rb * 68 + k0 + qi];
                a[mt][1] = A[(rb + 8) * 68 + k0 + qi];
                a[mt][2] = A[rb * 68 + k0 + 4 + qi];
                a[mt][3] = A[(rb + 8) * 68 + k0 + 4 + qi];
            }
#pragma unroll
            for (int nt = 0; nt < 4; nt++) {
                int nb = wn * 32 + nt * 8 + gi;
                b[nt][0] = B[nb * 68 + k0 + qi];
                b[nt][1] = B[nb * 68 + k0 + 4 + qi];
            }
#pragma unroll
            for (int mt = 0; mt < 4; mt++)
#pragma unroll
                for (int nt = 0; nt < 4; nt++)
                    mma8(acc[mt][nt], a[mt], b[nt]);
        }
        __syncthreads();
    }
#pragma unroll
    for (int mt = 0; mt < 4; mt++) {
        int r0 = m0 + wm * 64 + mt * 16 + gi;
#pragma unroll
        for (int nt = 0; nt < 4; nt++) {
            int c0 = o0 + wn * 32 + nt * 8 + 2 * qi;
            float b0 = bias[c0], b1 = bias[c0 + 1];
            out[(size_t)r0 * DD + c0]           = acc[mt][nt][0] + b0;
            out[(size_t)r0 * DD + c0 + 1]       = acc[mt][nt][1] + b1;
            out[(size_t)(r0 + 8) * DD + c0]     = acc[mt][nt][2] + b0;
            out[(size_t)(r0 + 8) * DD + c0 + 1] = acc[mt][nt][3] + b1;
        }
    }
}

// ---------------- launch ----------------------------------------------------
extern "C" void kernel_launch(void* const* d_in, const int* in_sizes, int n_in,
                              void* d_out, int out_size) {
    const float* values = (const float*)d_in[0];
    const float* keys   = (const float*)d_in[1];
    const float* query  = (const float*)d_in[2];
    const float* ovals  = (const float*)d_in[3];
    const float* okeys  = (const float*)d_in[4];
    const float* Wv     = (const float*)d_in[5];
    const float* Wk     = (const float*)d_in[6];
    const float* Wq     = (const float*)d_in[7];
    const float* fcw    = (const float*)d_in[8];
    const float* fcb    = (const float*)d_in[9];
    float* out = (float*)d_out;

    const int SMEM_QK = 3 * 128 * 72 * 2 + 128 * 136 * 2; // 90112 -> 2 CTAs/SM
    const int SMEM_FC = 4 * 128 * 68 * 4;                 // 139264
    const int SMEM_PJ = (2 * 128 + 2 * 64) * 68 * 4;      // 104448
    cudaFuncSetAttribute(proj_tc_kernel,
        cudaFuncAttributeMaxDynamicSharedMemorySize, SMEM_PJ);
    cudaFuncSetAttribute(qk_tc_kernel,
        cudaFuncAttributeMaxDynamicSharedMemorySize, SMEM_QK);
    cudaFuncSetAttribute(fc_tc_kernel,
        cudaFuncAttributeMaxDynamicSharedMemorySize, SMEM_FC);

    proj_tc_kernel<<<dim3(512, 5), 256, SMEM_PJ>>>(
        query, keys, values, okeys, ovals, Wq, Wk, Wv);
    wcvt_kernel<<<DD * DD / 256, 256>>>(fcw);
    diag_kernel<<<NROW / 8, 256>>>();
    qk_tc_kernel<<<dim3(QTILES, NHTOT), 256, SMEM_QK>>>();
    colsum2_kernel<<<dim3(16, NHTOT, 4), 256>>>();
    reduce2_kernel<<<NROW / 256, 256>>>();
    pre_kernel<<<NB * LL * DD / 256, 256>>>();
    fc_tc_kernel<<<dim3(DD / 128, NB * LL / 128), 256, SMEM_FC>>>(fcb, out);
}